// round 1
// baseline (speedup 1.0000x reference)
#include <cuda_runtime.h>
#include <cstdint>

// Problem constants
constexpr int Bn  = 8;
constexpr int Ss  = 4096;
constexpr int Dd  = 640;
constexpr int Tt  = 77;
constexpr int DEe = 768;
constexpr int Hh  = 10;
constexpr int HDd = 64;
constexpr int Rr  = 64;
constexpr float LN_EPS = 1e-5f;

// ---------------- scratch (static device globals; no allocation) ----------------
__device__ float g_q [(size_t)Bn*Ss*Dd];
__device__ float g_k [(size_t)Bn*Tt*Dd];
__device__ float g_v [(size_t)Bn*Tt*Dd];
__device__ float g_Fg[(size_t)Bn*Ss*Dd];
__device__ float g_F0[(size_t)Bn*Ss*Dd];
__device__ float g_F1[(size_t)Bn*Ss*Dd];
__device__ float g_bl[(size_t)Bn*Ss*Dd];
__device__ float g_uT0[Rr*Dd];
__device__ float g_uT1[Rr*Dd];

// ---------------- SGEMM: C[m,n] = sum_k A[m,k]*W[n,k] (+ bias[n]) ----------------
// A row-major MxK, W row-major NxK (both K-contiguous). 128x128x16 tile, 8x8/thread.
template<bool HAS_BIAS>
__global__ __launch_bounds__(256)
void sgemm_abt_kernel(const float* __restrict__ A, const float* __restrict__ W,
                      const float* __restrict__ bias, float* __restrict__ C,
                      int M, int N, int K)
{
    constexpr int BM = 128, BN = 128, BK = 16;
    __shared__ float As[BK][BM];
    __shared__ float Bs[BK][BN];

    const int tid = threadIdx.x;
    const int m0 = blockIdx.y * BM;
    const int n0 = blockIdx.x * BN;
    const int tx = tid & 15;         // 0..15 (n dir)
    const int ty = tid >> 4;         // 0..15 (m dir)
    const int lrow = tid >> 2;       // 0..63
    const int lk   = (tid & 3) * 4;  // 0,4,8,12

    float acc[8][8];
#pragma unroll
    for (int i = 0; i < 8; i++)
#pragma unroll
        for (int j = 0; j < 8; j++) acc[i][j] = 0.f;

    for (int k0 = 0; k0 < K; k0 += BK) {
#pragma unroll
        for (int p = 0; p < 2; p++) {
            const int r = lrow + p * 64;
            // A tile
            {
                const int gm = m0 + r;
                float4 va = make_float4(0.f, 0.f, 0.f, 0.f);
                if (gm < M) va = *(const float4*)(A + (size_t)gm * K + k0 + lk);
                As[lk + 0][r] = va.x; As[lk + 1][r] = va.y;
                As[lk + 2][r] = va.z; As[lk + 3][r] = va.w;
            }
            // B tile (rows of W)
            {
                const int gn = n0 + r;
                float4 vb = make_float4(0.f, 0.f, 0.f, 0.f);
                if (gn < N) vb = *(const float4*)(W + (size_t)gn * K + k0 + lk);
                Bs[lk + 0][r] = vb.x; Bs[lk + 1][r] = vb.y;
                Bs[lk + 2][r] = vb.z; Bs[lk + 3][r] = vb.w;
            }
        }
        __syncthreads();
#pragma unroll
        for (int kk = 0; kk < BK; kk++) {
            float ra[8], rb[8];
            *(float4*)&ra[0] = *(const float4*)&As[kk][ty * 8];
            *(float4*)&ra[4] = *(const float4*)&As[kk][ty * 8 + 4];
            *(float4*)&rb[0] = *(const float4*)&Bs[kk][tx * 8];
            *(float4*)&rb[4] = *(const float4*)&Bs[kk][tx * 8 + 4];
#pragma unroll
            for (int i = 0; i < 8; i++)
#pragma unroll
                for (int j = 0; j < 8; j++)
                    acc[i][j] = fmaf(ra[i], rb[j], acc[i][j]);
        }
        __syncthreads();
    }

#pragma unroll
    for (int i = 0; i < 8; i++) {
        const int gm = m0 + ty * 8 + i;
        if (gm >= M) continue;
#pragma unroll
        for (int j = 0; j < 8; j += 4) {
            const int gn = n0 + tx * 8 + j;
            float4 v;
            v.x = acc[i][j + 0]; v.y = acc[i][j + 1];
            v.z = acc[i][j + 2]; v.w = acc[i][j + 3];
            if (HAS_BIAS) {
                const float4 bv = *(const float4*)(bias + gn);
                v.x += bv.x; v.y += bv.y; v.z += bv.z; v.w += bv.w;
            }
            *(float4*)(C + (size_t)gm * N + gn) = v;
        }
    }
}

// ---------------- transpose up-proj weights: (D,R) -> (R,D) ----------------
__global__ void transpose_up_kernel(const float* __restrict__ u0,
                                    const float* __restrict__ u1,
                                    float* __restrict__ t0,
                                    float* __restrict__ t1)
{
    const int i = blockIdx.x * blockDim.x + threadIdx.x;
    if (i < Dd * Rr) {
        const int d = i / Rr;
        const int r = i % Rr;
        t0[r * Dd + d] = u0[i];
        t1[r * Dd + d] = u1[i];
    }
}

// ---------------- fused attention: global + 2 entity attentions ----------------
// grid (S/128, B*H), 128 threads. One thread per query.
constexpr int ATT_QT = 128;
constexpr int QPAD   = 68;  // padded q row stride (16B aligned, conflict-benign)
constexpr int ATT_SMEM_FLOATS = 2 * Tt * HDd + ATT_QT * QPAD + ATT_QT * Tt;

__global__ __launch_bounds__(128)
void attn_kernel(const float* __restrict__ q, const float* __restrict__ k,
                 const float* __restrict__ v,
                 const int* __restrict__ idx0, const int* __restrict__ idx1,
                 float* __restrict__ Fg, float* __restrict__ F0,
                 float* __restrict__ F1)
{
    extern __shared__ float sm[];
    float* Ksh = sm;                       // Tt*HDd
    float* Vsh = Ksh + Tt * HDd;           // Tt*HDd
    float* Qsh = Vsh + Tt * HDd;           // ATT_QT*QPAD
    float* Psh = Qsh + ATT_QT * QPAD;      // ATT_QT*Tt
    __shared__ int si0[8], si1[8];

    const int tid = threadIdx.x;
    const int b = blockIdx.y / Hh;
    const int h = blockIdx.y % Hh;
    const int s0 = blockIdx.x * ATT_QT;

    if (tid < 8) { si0[tid] = idx0[tid]; si1[tid] = idx1[tid]; }

    const float* kb = k + (size_t)b * Tt * Dd + h * HDd;
    const float* vb = v + (size_t)b * Tt * Dd + h * HDd;
    for (int i = tid; i < Tt * HDd; i += ATT_QT) {
        const int t = i >> 6, d = i & 63;
        Ksh[i] = kb[(size_t)t * Dd + d];
        Vsh[i] = vb[(size_t)t * Dd + d];
    }
    const float* qb = q + (size_t)(b * Ss + s0) * Dd + h * HDd;
    for (int i = tid; i < ATT_QT * HDd; i += ATT_QT) {
        const int r = i >> 6, d = i & 63;
        Qsh[r * QPAD + d] = qb[(size_t)r * Dd + d];
    }
    __syncthreads();

    // q row into registers
    float4 qr[16];
    const float4* qrow = (const float4*)&Qsh[tid * QPAD];
#pragma unroll
    for (int i = 0; i < 16; i++) qr[i] = qrow[i];

    float* prow = &Psh[tid * Tt];

    // global scores (also the superset for entity scores)
    for (int t = 0; t < Tt; t++) {
        const float4* kp = (const float4*)&Ksh[t * HDd];
        float a0 = 0.f, a1 = 0.f, a2 = 0.f, a3 = 0.f;
#pragma unroll
        for (int i = 0; i < 16; i++) {
            const float4 kv = kp[i];
            a0 = fmaf(qr[i].x, kv.x, a0);
            a1 = fmaf(qr[i].y, kv.y, a1);
            a2 = fmaf(qr[i].z, kv.z, a2);
            a3 = fmaf(qr[i].w, kv.w, a3);
        }
        prow[t] = ((a0 + a1) + (a2 + a3)) * 0.125f;
    }

    // gather raw entity scores before overwriting with exp
    float e0s[8], e1s[8];
#pragma unroll
    for (int j = 0; j < 8; j++) { e0s[j] = prow[si0[j]]; e1s[j] = prow[si1[j]]; }

    // global softmax (store unnormalized exp back into prow)
    float m = -1e30f;
    for (int t = 0; t < Tt; t++) m = fmaxf(m, prow[t]);
    float z = 0.f;
    for (int t = 0; t < Tt; t++) { const float p = expf(prow[t] - m); prow[t] = p; z += p; }
    const float invz = 1.f / z;

    // entity softmaxes
    float m0 = -1e30f, m1 = -1e30f;
#pragma unroll
    for (int j = 0; j < 8; j++) { m0 = fmaxf(m0, e0s[j]); m1 = fmaxf(m1, e1s[j]); }
    float z0 = 0.f, z1 = 0.f;
#pragma unroll
    for (int j = 0; j < 8; j++) {
        e0s[j] = expf(e0s[j] - m0); z0 += e0s[j];
        e1s[j] = expf(e1s[j] - m1); z1 += e1s[j];
    }
    const float invz0 = 1.f / z0, invz1 = 1.f / z1;

    const int s = s0 + tid;
    const size_t obase = (size_t)(b * Ss + s) * Dd + h * HDd;

    // global AV
    {
        float4 acc[16];
#pragma unroll
        for (int i = 0; i < 16; i++) acc[i] = make_float4(0.f, 0.f, 0.f, 0.f);
        for (int t = 0; t < Tt; t++) {
            const float p = prow[t];
            const float4* vp = (const float4*)&Vsh[t * HDd];
#pragma unroll
            for (int i = 0; i < 16; i++) {
                const float4 vv = vp[i];
                acc[i].x = fmaf(p, vv.x, acc[i].x);
                acc[i].y = fmaf(p, vv.y, acc[i].y);
                acc[i].z = fmaf(p, vv.z, acc[i].z);
                acc[i].w = fmaf(p, vv.w, acc[i].w);
            }
        }
        float4* og = (float4*)(Fg + obase);
#pragma unroll
        for (int i = 0; i < 16; i++) {
            float4 o = acc[i];
            o.x *= invz; o.y *= invz; o.z *= invz; o.w *= invz;
            og[i] = o;
        }
    }
    // entity 0 AV
    {
        float4 acc[16];
#pragma unroll
        for (int i = 0; i < 16; i++) acc[i] = make_float4(0.f, 0.f, 0.f, 0.f);
#pragma unroll
        for (int j = 0; j < 8; j++) {
            const float p = e0s[j];
            const float4* vp = (const float4*)&Vsh[si0[j] * HDd];
#pragma unroll
            for (int i = 0; i < 16; i++) {
                const float4 vv = vp[i];
                acc[i].x = fmaf(p, vv.x, acc[i].x);
                acc[i].y = fmaf(p, vv.y, acc[i].y);
                acc[i].z = fmaf(p, vv.z, acc[i].z);
                acc[i].w = fmaf(p, vv.w, acc[i].w);
            }
        }
        float4* og = (float4*)(F0 + obase);
#pragma unroll
        for (int i = 0; i < 16; i++) {
            float4 o = acc[i];
            o.x *= invz0; o.y *= invz0; o.z *= invz0; o.w *= invz0;
            og[i] = o;
        }
    }
    // entity 1 AV
    {
        float4 acc[16];
#pragma unroll
        for (int i = 0; i < 16; i++) acc[i] = make_float4(0.f, 0.f, 0.f, 0.f);
#pragma unroll
        for (int j = 0; j < 8; j++) {
            const float p = e1s[j];
            const float4* vp = (const float4*)&Vsh[si1[j] * HDd];
#pragma unroll
            for (int i = 0; i < 16; i++) {
                const float4 vv = vp[i];
                acc[i].x = fmaf(p, vv.x, acc[i].x);
                acc[i].y = fmaf(p, vv.y, acc[i].y);
                acc[i].z = fmaf(p, vv.z, acc[i].z);
                acc[i].w = fmaf(p, vv.w, acc[i].w);
            }
        }
        float4* og = (float4*)(F1 + obase);
#pragma unroll
        for (int i = 0; i < 16; i++) {
            float4 o = acc[i];
            o.x *= invz1; o.y *= invz1; o.z *= invz1; o.w *= invz1;
            og[i] = o;
        }
    }
}

// ---------------- fused adapters + compose + blend ----------------
// grid (B*S/NR), 256 threads. NR rows per block to amortize weight traffic.
constexpr int NR = 16;
constexpr int ADP_SMEM_FLOATS = 2 * NR * Dd + 2 * NR * Rr;

__global__ __launch_bounds__(256)
void adapter_kernel(const float* __restrict__ F0, const float* __restrict__ F1,
                    const float* __restrict__ Fg,
                    const float* __restrict__ ln0g, const float* __restrict__ ln0b,
                    const float* __restrict__ d0W,  const float* __restrict__ d0b,
                    const float* __restrict__ uT0,  const float* __restrict__ u0b,
                    const float* __restrict__ ln1g, const float* __restrict__ ln1b,
                    const float* __restrict__ d1W,  const float* __restrict__ d1b,
                    const float* __restrict__ uT1,  const float* __restrict__ u1b,
                    const float* __restrict__ blend_raw,
                    float* __restrict__ out)
{
    extern __shared__ float sm[];
    float* n0 = sm;                    // NR*Dd normalized adapter-0 inputs
    float* n1 = n0 + NR * Dd;          // NR*Dd
    float* hs = n1 + NR * Dd;          // [2][Rr][NR] (r-major, rows contiguous)

    const int tid = threadIdx.x;
    const int wid = tid >> 5;
    const int lane = tid & 31;
    const int row0 = blockIdx.x * NR;

    // ---- phase 1: LayerNorm (32 warp tasks: 2 adapters x NR rows) ----
    for (int task = wid; task < 2 * NR; task += 8) {
        const int a = task / NR;
        const int r = task % NR;
        const float* src = (a ? F1 : F0) + (size_t)(row0 + r) * Dd;
        float vals[20];
        float sum = 0.f;
#pragma unroll
        for (int i = 0; i < 20; i++) { vals[i] = src[lane + 32 * i]; sum += vals[i]; }
#pragma unroll
        for (int o = 16; o > 0; o >>= 1) sum += __shfl_xor_sync(0xffffffffu, sum, o);
        const float mean = sum * (1.f / Dd);
        float vs = 0.f;
#pragma unroll
        for (int i = 0; i < 20; i++) { const float dv = vals[i] - mean; vs = fmaf(dv, dv, vs); }
#pragma unroll
        for (int o = 16; o > 0; o >>= 1) vs += __shfl_xor_sync(0xffffffffu, vs, o);
        const float rstd = rsqrtf(vs * (1.f / Dd) + LN_EPS);
        const float* g  = a ? ln1g : ln0g;
        const float* be = a ? ln1b : ln0b;
        float* dst = (a ? n1 : n0) + r * Dd;
#pragma unroll
        for (int i = 0; i < 20; i++) {
            const int d = lane + 32 * i;
            dst[d] = (vals[i] - mean) * rstd * g[d] + be[d];
        }
    }
    __syncthreads();

    // ---- phase 2: down-proj + SiLU (128 warp tasks: 2 adapters x Rr) ----
    for (int task = wid; task < 2 * Rr; task += 8) {
        const int a = task / Rr;
        const int r = task % Rr;
        const float* W = (a ? d1W : d0W) + (size_t)r * Dd;
        const float* nn = a ? n1 : n0;
        float acc[NR];
#pragma unroll
        for (int rw = 0; rw < NR; rw++) acc[rw] = 0.f;
        for (int i = 0; i < 20; i++) {
            const float w = W[lane + 32 * i];
#pragma unroll
            for (int rw = 0; rw < NR; rw++)
                acc[rw] = fmaf(w, nn[rw * Dd + lane + 32 * i], acc[rw]);
        }
#pragma unroll
        for (int rw = 0; rw < NR; rw++) {
#pragma unroll
            for (int o = 16; o > 0; o >>= 1)
                acc[rw] += __shfl_xor_sync(0xffffffffu, acc[rw], o);
        }
        if (lane == 0) {
            const float db = (a ? d1b : d0b)[r];
            float* hdst = hs + a * (Rr * NR) + r * NR;
#pragma unroll
            for (int rw = 0; rw < NR; rw++) {
                const float x = acc[rw] + db;
                hdst[rw] = x / (1.f + expf(-x));   // SiLU
            }
        }
    }
    __syncthreads();

    // ---- phase 3: up-proj + compose + blend ----
    const float braw = *blend_raw;
    const float blend = 1.f / (1.f + expf(-braw));
    const float oneminus = 1.f - blend;

    for (int d = tid; d < Dd; d += 256) {
        float4 a0acc[4], a1acc[4];
        const float ub0 = u0b[d], ub1 = u1b[d];
#pragma unroll
        for (int c = 0; c < 4; c++) {
            a0acc[c] = make_float4(ub0, ub0, ub0, ub0);
            a1acc[c] = make_float4(ub1, ub1, ub1, ub1);
        }
        for (int r = 0; r < Rr; r++) {
            const float w0 = uT0[(size_t)r * Dd + d];
            const float w1 = uT1[(size_t)r * Dd + d];
            const float4* h0p = (const float4*)&hs[r * NR];
            const float4* h1p = (const float4*)&hs[Rr * NR + r * NR];
#pragma unroll
            for (int c = 0; c < 4; c++) {
                const float4 h0v = h0p[c];
                const float4 h1v = h1p[c];
                a0acc[c].x = fmaf(h0v.x, w0, a0acc[c].x);
                a0acc[c].y = fmaf(h0v.y, w0, a0acc[c].y);
                a0acc[c].z = fmaf(h0v.z, w0, a0acc[c].z);
                a0acc[c].w = fmaf(h0v.w, w0, a0acc[c].w);
                a1acc[c].x = fmaf(h1v.x, w1, a1acc[c].x);
                a1acc[c].y = fmaf(h1v.y, w1, a1acc[c].y);
                a1acc[c].z = fmaf(h1v.z, w1, a1acc[c].z);
                a1acc[c].w = fmaf(h1v.w, w1, a1acc[c].w);
            }
        }
        const float* a0f = (const float*)a0acc;
        const float* a1f = (const float*)a1acc;
#pragma unroll
        for (int rw = 0; rw < NR; rw++) {
            const size_t gi = (size_t)(row0 + rw) * Dd + d;
            const float x0 = F0[gi], x1 = F1[gi], fg = Fg[gi];
            const float comp = (x0 + a0f[rw] + x1 + a1f[rw] + fg) * (1.f / 3.f);
            out[gi] = blend * comp + oneminus * fg;
        }
    }
}

// ---------------- launch ----------------
extern "C" void kernel_launch(void* const* d_in, const int* in_sizes, int n_in,
                              void* d_out, int out_size)
{
    (void)in_sizes; (void)n_in; (void)out_size;
    const float* hs   = (const float*)d_in[0];
    const float* enc  = (const float*)d_in[1];
    const float* Wq   = (const float*)d_in[2];
    const float* Wk   = (const float*)d_in[3];
    const float* Wv   = (const float*)d_in[4];
    const float* Wo   = (const float*)d_in[5];
    const float* bo   = (const float*)d_in[6];
    const float* ln0g = (const float*)d_in[7];
    const float* ln0b = (const float*)d_in[8];
    const float* d0W  = (const float*)d_in[9];
    const float* d0b  = (const float*)d_in[10];
    const float* u0W  = (const float*)d_in[11];
    const float* u0b  = (const float*)d_in[12];
    const float* ln1g = (const float*)d_in[13];
    const float* ln1b = (const float*)d_in[14];
    const float* d1W  = (const float*)d_in[15];
    const float* d1b  = (const float*)d_in[16];
    const float* u1W  = (const float*)d_in[17];
    const float* u1b  = (const float*)d_in[18];
    const float* sbr  = (const float*)d_in[19];
    const int*   idx0 = (const int*)d_in[20];
    const int*   idx1 = (const int*)d_in[21];
    float* out = (float*)d_out;

    float *pq, *pk, *pv, *pFg, *pF0, *pF1, *pbl, *pT0, *pT1;
    cudaGetSymbolAddress((void**)&pq,  g_q);
    cudaGetSymbolAddress((void**)&pk,  g_k);
    cudaGetSymbolAddress((void**)&pv,  g_v);
    cudaGetSymbolAddress((void**)&pFg, g_Fg);
    cudaGetSymbolAddress((void**)&pF0, g_F0);
    cudaGetSymbolAddress((void**)&pF1, g_F1);
    cudaGetSymbolAddress((void**)&pbl, g_bl);
    cudaGetSymbolAddress((void**)&pT0, g_uT0);
    cudaGetSymbolAddress((void**)&pT1, g_uT1);

    const int att_smem = ATT_SMEM_FLOATS * (int)sizeof(float);
    const int adp_smem = ADP_SMEM_FLOATS * (int)sizeof(float);
    cudaFuncSetAttribute(attn_kernel, cudaFuncAttributeMaxDynamicSharedMemorySize, att_smem);
    cudaFuncSetAttribute(adapter_kernel, cudaFuncAttributeMaxDynamicSharedMemorySize, adp_smem);

    const int MKV = Bn * Tt;          // 616
    const int MQ  = Bn * Ss;          // 32768

    // K/V projections: (B*T, DE) x (D, DE)^T
    {
        dim3 grid(Dd / 128, (MKV + 127) / 128);
        sgemm_abt_kernel<false><<<grid, 256>>>(enc, Wk, nullptr, pk, MKV, Dd, DEe);
        sgemm_abt_kernel<false><<<grid, 256>>>(enc, Wv, nullptr, pv, MKV, Dd, DEe);
    }
    // Q projection: (B*S, D) x (D, D)^T
    {
        dim3 grid(Dd / 128, MQ / 128);
        sgemm_abt_kernel<false><<<grid, 256>>>(hs, Wq, nullptr, pq, MQ, Dd, Dd);
    }
    // transpose up-proj weights
    transpose_up_kernel<<<(Dd * Rr + 255) / 256, 256>>>(u0W, u1W, pT0, pT1);

    // fused attention
    {
        dim3 grid(Ss / ATT_QT, Bn * Hh);
        attn_kernel<<<grid, ATT_QT, att_smem>>>(pq, pk, pv, idx0, idx1, pFg, pF0, pF1);
    }
    // fused adapters + compose + blend
    adapter_kernel<<<MQ / NR, 256, adp_smem>>>(pF0, pF1, pFg,
                                               ln0g, ln0b, d0W, d0b, pT0, u0b,
                                               ln1g, ln1b, d1W, d1b, pT1, u1b,
                                               sbr, pbl);
    // output projection + bias
    {
        dim3 grid(Dd / 128, MQ / 128);
        sgemm_abt_kernel<true><<<grid, 256>>>(pbl, Wo, bo, out, MQ, Dd, Dd);
    }
}

// round 2
// speedup vs baseline: 1.5721x; 1.5721x over previous
#include <cuda_runtime.h>
#include <cstdint>

// Problem constants
constexpr int Bn  = 8;
constexpr int Ss  = 4096;
constexpr int Dd  = 640;
constexpr int Tt  = 77;
constexpr int DEe = 768;
constexpr int Hh  = 10;
constexpr int HDd = 64;
constexpr int Rr  = 64;
constexpr float LN_EPS = 1e-5f;

// ---------------- scratch (static device globals; no allocation) ----------------
__device__ float g_q [(size_t)Bn*Ss*Dd];
__device__ float g_k [(size_t)Bn*Tt*Dd];
__device__ float g_v [(size_t)Bn*Tt*Dd];
__device__ float g_Fg[(size_t)Bn*Ss*Dd];
__device__ float g_F0[(size_t)Bn*Ss*Dd];
__device__ float g_F1[(size_t)Bn*Ss*Dd];
__device__ float g_bl[(size_t)Bn*Ss*Dd];
__device__ float g_uT0[Rr*Dd];
__device__ float g_uT1[Rr*Dd];

// ================= TF32 tensor-core GEMM: C[m,n] = sum_k A[m,k]*W[n,k] (+bias) ==
// A: MxK row-major fp32.  W: NxK row-major fp32.  Inputs rounded to tf32 once
// during smem staging.  Block tile 128x128, BK=32, 8 warps of 64x32 warp tiles,
// mma.sync.m16n8k8.tf32 atoms.
constexpr int GLDA = 36;   // smem row stride in floats (32 + 4 pad)

__device__ __forceinline__ uint32_t f2tf32(float x) {
    uint32_t r;
    asm("cvt.rna.tf32.f32 %0, %1;" : "=r"(r) : "f"(x));
    return r;
}

__device__ __forceinline__ void mma_tf32(float c[4], const uint32_t a[4], const uint32_t b[2]) {
    asm volatile(
        "mma.sync.aligned.m16n8k8.row.col.f32.tf32.tf32.f32 "
        "{%0,%1,%2,%3}, {%4,%5,%6,%7}, {%8,%9}, {%0,%1,%2,%3};"
        : "+f"(c[0]), "+f"(c[1]), "+f"(c[2]), "+f"(c[3])
        : "r"(a[0]), "r"(a[1]), "r"(a[2]), "r"(a[3]), "r"(b[0]), "r"(b[1]));
}

template<bool HAS_BIAS>
__global__ __launch_bounds__(256)
void gemm_tf32_kernel(const float* __restrict__ A, const float* __restrict__ W,
                      const float* __restrict__ bias, float* __restrict__ C,
                      int M, int N, int K)
{
    __shared__ uint32_t As[128 * GLDA];
    __shared__ uint32_t Bs[128 * GLDA];

    const int tid  = threadIdx.x;
    const int wid  = tid >> 5;
    const int lane = tid & 31;
    const int g    = lane >> 2;      // 0..7
    const int tg   = lane & 3;       // 0..3

    const int m0 = blockIdx.y * 128;
    const int n0 = blockIdx.x * 128;
    const int wm = (wid & 1) * 64;   // warp m offset in block
    const int wn = (wid >> 1) * 32;  // warp n offset in block

    float acc[4][4][4];
#pragma unroll
    for (int i = 0; i < 4; i++)
#pragma unroll
        for (int j = 0; j < 4; j++)
#pragma unroll
            for (int r = 0; r < 4; r++) acc[i][j][r] = 0.f;

    for (int k0 = 0; k0 < K; k0 += 32) {
        // stage A,B tiles (128 rows x 32 k) with tf32 rounding
#pragma unroll
        for (int p = 0; p < 4; p++) {
            const int idx = p * 256 + tid;        // 0..1023 over [128 rows][8 float4 segs]
            const int row = idx >> 3;
            const int seg = idx & 7;
            // A
            {
                const int gm = m0 + row;
                float4 v = make_float4(0.f, 0.f, 0.f, 0.f);
                if (gm < M) v = *(const float4*)(A + (size_t)gm * K + k0 + seg * 4);
                uint4 t;
                t.x = f2tf32(v.x); t.y = f2tf32(v.y); t.z = f2tf32(v.z); t.w = f2tf32(v.w);
                *(uint4*)&As[row * GLDA + seg * 4] = t;
            }
            // B (rows of W)
            {
                const int gn = n0 + row;
                float4 v = make_float4(0.f, 0.f, 0.f, 0.f);
                if (gn < N) v = *(const float4*)(W + (size_t)gn * K + k0 + seg * 4);
                uint4 t;
                t.x = f2tf32(v.x); t.y = f2tf32(v.y); t.z = f2tf32(v.z); t.w = f2tf32(v.w);
                *(uint4*)&Bs[row * GLDA + seg * 4] = t;
            }
        }
        __syncthreads();

#pragma unroll
        for (int ka = 0; ka < 4; ka++) {
            const int kc = ka * 8;
            uint32_t afr[4][4];
            uint32_t bfr[4][2];
#pragma unroll
            for (int i = 0; i < 4; i++) {
                const int r0 = wm + 16 * i + g;
                afr[i][0] = As[r0 * GLDA + kc + tg];
                afr[i][1] = As[(r0 + 8) * GLDA + kc + tg];
                afr[i][2] = As[r0 * GLDA + kc + tg + 4];
                afr[i][3] = As[(r0 + 8) * GLDA + kc + tg + 4];
            }
#pragma unroll
            for (int j = 0; j < 4; j++) {
                const int nrow = wn + 8 * j + g;
                bfr[j][0] = Bs[nrow * GLDA + kc + tg];
                bfr[j][1] = Bs[nrow * GLDA + kc + tg + 4];
            }
#pragma unroll
            for (int i = 0; i < 4; i++)
#pragma unroll
                for (int j = 0; j < 4; j++)
                    mma_tf32(acc[i][j], afr[i], bfr[j]);
        }
        __syncthreads();
    }

    // epilogue
#pragma unroll
    for (int i = 0; i < 4; i++) {
        const int rowA = m0 + wm + 16 * i + g;
        const int rowB = rowA + 8;
#pragma unroll
        for (int j = 0; j < 4; j++) {
            const int col = n0 + wn + 8 * j + 2 * tg;
            float2 bv = make_float2(0.f, 0.f);
            if (HAS_BIAS) bv = *(const float2*)(bias + col);
            if (rowA < M) {
                float2 v = make_float2(acc[i][j][0] + bv.x, acc[i][j][1] + bv.y);
                *(float2*)(C + (size_t)rowA * N + col) = v;
            }
            if (rowB < M) {
                float2 v = make_float2(acc[i][j][2] + bv.x, acc[i][j][3] + bv.y);
                *(float2*)(C + (size_t)rowB * N + col) = v;
            }
        }
    }
}

// ---------------- transpose up-proj weights: (D,R) -> (R,D) ----------------
__global__ void transpose_up_kernel(const float* __restrict__ u0,
                                    const float* __restrict__ u1,
                                    float* __restrict__ t0,
                                    float* __restrict__ t1)
{
    const int i = blockIdx.x * blockDim.x + threadIdx.x;
    if (i < Dd * Rr) {
        const int d = i / Rr;
        const int r = i % Rr;
        t0[r * Dd + d] = u0[i];
        t1[r * Dd + d] = u1[i];
    }
}

// ---------------- fused attention: global + 2 entity attentions ----------------
// grid (S/128, B*H), 128 threads. One thread per query.
constexpr int ATT_QT = 128;
constexpr int QPAD   = 68;
constexpr int ATT_SMEM_FLOATS = 2 * Tt * HDd + ATT_QT * QPAD + ATT_QT * Tt;

__global__ __launch_bounds__(128)
void attn_kernel(const float* __restrict__ q, const float* __restrict__ k,
                 const float* __restrict__ v,
                 const int* __restrict__ idx0, const int* __restrict__ idx1,
                 float* __restrict__ Fg, float* __restrict__ F0,
                 float* __restrict__ F1)
{
    extern __shared__ float sm[];
    float* Ksh = sm;                       // Tt*HDd
    float* Vsh = Ksh + Tt * HDd;           // Tt*HDd
    float* Qsh = Vsh + Tt * HDd;           // ATT_QT*QPAD
    float* Psh = Qsh + ATT_QT * QPAD;      // ATT_QT*Tt
    __shared__ int si0[8], si1[8];

    const int tid = threadIdx.x;
    const int b = blockIdx.y / Hh;
    const int h = blockIdx.y % Hh;
    const int s0 = blockIdx.x * ATT_QT;

    if (tid < 8) { si0[tid] = idx0[tid]; si1[tid] = idx1[tid]; }

    const float* kb = k + (size_t)b * Tt * Dd + h * HDd;
    const float* vb = v + (size_t)b * Tt * Dd + h * HDd;
    for (int i = tid; i < Tt * HDd; i += ATT_QT) {
        const int t = i >> 6, d = i & 63;
        Ksh[i] = kb[(size_t)t * Dd + d];
        Vsh[i] = vb[(size_t)t * Dd + d];
    }
    const float* qb = q + (size_t)(b * Ss + s0) * Dd + h * HDd;
    for (int i = tid; i < ATT_QT * HDd; i += ATT_QT) {
        const int r = i >> 6, d = i & 63;
        Qsh[r * QPAD + d] = qb[(size_t)r * Dd + d];
    }
    __syncthreads();

    float4 qr[16];
    const float4* qrow = (const float4*)&Qsh[tid * QPAD];
#pragma unroll
    for (int i = 0; i < 16; i++) qr[i] = qrow[i];

    float* prow = &Psh[tid * Tt];

    for (int t = 0; t < Tt; t++) {
        const float4* kp = (const float4*)&Ksh[t * HDd];
        float a0 = 0.f, a1 = 0.f, a2 = 0.f, a3 = 0.f;
#pragma unroll
        for (int i = 0; i < 16; i++) {
            const float4 kv = kp[i];
            a0 = fmaf(qr[i].x, kv.x, a0);
            a1 = fmaf(qr[i].y, kv.y, a1);
            a2 = fmaf(qr[i].z, kv.z, a2);
            a3 = fmaf(qr[i].w, kv.w, a3);
        }
        prow[t] = ((a0 + a1) + (a2 + a3)) * 0.125f;
    }

    float e0s[8], e1s[8];
#pragma unroll
    for (int j = 0; j < 8; j++) { e0s[j] = prow[si0[j]]; e1s[j] = prow[si1[j]]; }

    float m = -1e30f;
    for (int t = 0; t < Tt; t++) m = fmaxf(m, prow[t]);
    float z = 0.f;
    for (int t = 0; t < Tt; t++) { const float p = expf(prow[t] - m); prow[t] = p; z += p; }
    const float invz = 1.f / z;

    float m0 = -1e30f, m1 = -1e30f;
#pragma unroll
    for (int j = 0; j < 8; j++) { m0 = fmaxf(m0, e0s[j]); m1 = fmaxf(m1, e1s[j]); }
    float z0 = 0.f, z1 = 0.f;
#pragma unroll
    for (int j = 0; j < 8; j++) {
        e0s[j] = expf(e0s[j] - m0); z0 += e0s[j];
        e1s[j] = expf(e1s[j] - m1); z1 += e1s[j];
    }
    const float invz0 = 1.f / z0, invz1 = 1.f / z1;

    const int s = s0 + tid;
    const size_t obase = (size_t)(b * Ss + s) * Dd + h * HDd;

    {
        float4 acc[16];
#pragma unroll
        for (int i = 0; i < 16; i++) acc[i] = make_float4(0.f, 0.f, 0.f, 0.f);
        for (int t = 0; t < Tt; t++) {
            const float p = prow[t];
            const float4* vp = (const float4*)&Vsh[t * HDd];
#pragma unroll
            for (int i = 0; i < 16; i++) {
                const float4 vv = vp[i];
                acc[i].x = fmaf(p, vv.x, acc[i].x);
                acc[i].y = fmaf(p, vv.y, acc[i].y);
                acc[i].z = fmaf(p, vv.z, acc[i].z);
                acc[i].w = fmaf(p, vv.w, acc[i].w);
            }
        }
        float4* og = (float4*)(Fg + obase);
#pragma unroll
        for (int i = 0; i < 16; i++) {
            float4 o = acc[i];
            o.x *= invz; o.y *= invz; o.z *= invz; o.w *= invz;
            og[i] = o;
        }
    }
    {
        float4 acc[16];
#pragma unroll
        for (int i = 0; i < 16; i++) acc[i] = make_float4(0.f, 0.f, 0.f, 0.f);
#pragma unroll
        for (int j = 0; j < 8; j++) {
            const float p = e0s[j];
            const float4* vp = (const float4*)&Vsh[si0[j] * HDd];
#pragma unroll
            for (int i = 0; i < 16; i++) {
                const float4 vv = vp[i];
                acc[i].x = fmaf(p, vv.x, acc[i].x);
                acc[i].y = fmaf(p, vv.y, acc[i].y);
                acc[i].z = fmaf(p, vv.z, acc[i].z);
                acc[i].w = fmaf(p, vv.w, acc[i].w);
            }
        }
        float4* og = (float4*)(F0 + obase);
#pragma unroll
        for (int i = 0; i < 16; i++) {
            float4 o = acc[i];
            o.x *= invz0; o.y *= invz0; o.z *= invz0; o.w *= invz0;
            og[i] = o;
        }
    }
    {
        float4 acc[16];
#pragma unroll
        for (int i = 0; i < 16; i++) acc[i] = make_float4(0.f, 0.f, 0.f, 0.f);
#pragma unroll
        for (int j = 0; j < 8; j++) {
            const float p = e1s[j];
            const float4* vp = (const float4*)&Vsh[si1[j] * HDd];
#pragma unroll
            for (int i = 0; i < 16; i++) {
                const float4 vv = vp[i];
                acc[i].x = fmaf(p, vv.x, acc[i].x);
                acc[i].y = fmaf(p, vv.y, acc[i].y);
                acc[i].z = fmaf(p, vv.z, acc[i].z);
                acc[i].w = fmaf(p, vv.w, acc[i].w);
            }
        }
        float4* og = (float4*)(F1 + obase);
#pragma unroll
        for (int i = 0; i < 16; i++) {
            float4 o = acc[i];
            o.x *= invz1; o.y *= invz1; o.z *= invz1; o.w *= invz1;
            og[i] = o;
        }
    }
}

// ---------------- fused adapters + compose + blend ----------------
constexpr int NR = 16;
constexpr int ADP_SMEM_FLOATS = 2 * NR * Dd + 2 * NR * Rr;

__global__ __launch_bounds__(256)
void adapter_kernel(const float* __restrict__ F0, const float* __restrict__ F1,
                    const float* __restrict__ Fg,
                    const float* __restrict__ ln0g, const float* __restrict__ ln0b,
                    const float* __restrict__ d0W,  const float* __restrict__ d0b,
                    const float* __restrict__ uT0,  const float* __restrict__ u0b,
                    const float* __restrict__ ln1g, const float* __restrict__ ln1b,
                    const float* __restrict__ d1W,  const float* __restrict__ d1b,
                    const float* __restrict__ uT1,  const float* __restrict__ u1b,
                    const float* __restrict__ blend_raw,
                    float* __restrict__ out)
{
    extern __shared__ float sm[];
    float* n0 = sm;
    float* n1 = n0 + NR * Dd;
    float* hs = n1 + NR * Dd;

    const int tid = threadIdx.x;
    const int wid = tid >> 5;
    const int lane = tid & 31;
    const int row0 = blockIdx.x * NR;

    for (int task = wid; task < 2 * NR; task += 8) {
        const int a = task / NR;
        const int r = task % NR;
        const float* src = (a ? F1 : F0) + (size_t)(row0 + r) * Dd;
        float vals[20];
        float sum = 0.f;
#pragma unroll
        for (int i = 0; i < 20; i++) { vals[i] = src[lane + 32 * i]; sum += vals[i]; }
#pragma unroll
        for (int o = 16; o > 0; o >>= 1) sum += __shfl_xor_sync(0xffffffffu, sum, o);
        const float mean = sum * (1.f / Dd);
        float vs = 0.f;
#pragma unroll
        for (int i = 0; i < 20; i++) { const float dv = vals[i] - mean; vs = fmaf(dv, dv, vs); }
#pragma unroll
        for (int o = 16; o > 0; o >>= 1) vs += __shfl_xor_sync(0xffffffffu, vs, o);
        const float rstd = rsqrtf(vs * (1.f / Dd) + LN_EPS);
        const float* g  = a ? ln1g : ln0g;
        const float* be = a ? ln1b : ln0b;
        float* dst = (a ? n1 : n0) + r * Dd;
#pragma unroll
        for (int i = 0; i < 20; i++) {
            const int d = lane + 32 * i;
            dst[d] = (vals[i] - mean) * rstd * g[d] + be[d];
        }
    }
    __syncthreads();

    for (int task = wid; task < 2 * Rr; task += 8) {
        const int a = task / Rr;
        const int r = task % Rr;
        const float* W = (a ? d1W : d0W) + (size_t)r * Dd;
        const float* nn = a ? n1 : n0;
        float acc[NR];
#pragma unroll
        for (int rw = 0; rw < NR; rw++) acc[rw] = 0.f;
        for (int i = 0; i < 20; i++) {
            const float w = W[lane + 32 * i];
#pragma unroll
            for (int rw = 0; rw < NR; rw++)
                acc[rw] = fmaf(w, nn[rw * Dd + lane + 32 * i], acc[rw]);
        }
#pragma unroll
        for (int rw = 0; rw < NR; rw++) {
#pragma unroll
            for (int o = 16; o > 0; o >>= 1)
                acc[rw] += __shfl_xor_sync(0xffffffffu, acc[rw], o);
        }
        if (lane == 0) {
            const float db = (a ? d1b : d0b)[r];
            float* hdst = hs + a * (Rr * NR) + r * NR;
#pragma unroll
            for (int rw = 0; rw < NR; rw++) {
                const float x = acc[rw] + db;
                hdst[rw] = x / (1.f + expf(-x));
            }
        }
    }
    __syncthreads();

    const float braw = *blend_raw;
    const float blend = 1.f / (1.f + expf(-braw));
    const float oneminus = 1.f - blend;

    for (int d = tid; d < Dd; d += 256) {
        float4 a0acc[4], a1acc[4];
        const float ub0 = u0b[d], ub1 = u1b[d];
#pragma unroll
        for (int c = 0; c < 4; c++) {
            a0acc[c] = make_float4(ub0, ub0, ub0, ub0);
            a1acc[c] = make_float4(ub1, ub1, ub1, ub1);
        }
        for (int r = 0; r < Rr; r++) {
            const float w0 = uT0[(size_t)r * Dd + d];
            const float w1 = uT1[(size_t)r * Dd + d];
            const float4* h0p = (const float4*)&hs[r * NR];
            const float4* h1p = (const float4*)&hs[Rr * NR + r * NR];
#pragma unroll
            for (int c = 0; c < 4; c++) {
                const float4 h0v = h0p[c];
                const float4 h1v = h1p[c];
                a0acc[c].x = fmaf(h0v.x, w0, a0acc[c].x);
                a0acc[c].y = fmaf(h0v.y, w0, a0acc[c].y);
                a0acc[c].z = fmaf(h0v.z, w0, a0acc[c].z);
                a0acc[c].w = fmaf(h0v.w, w0, a0acc[c].w);
                a1acc[c].x = fmaf(h1v.x, w1, a1acc[c].x);
                a1acc[c].y = fmaf(h1v.y, w1, a1acc[c].y);
                a1acc[c].z = fmaf(h1v.z, w1, a1acc[c].z);
                a1acc[c].w = fmaf(h1v.w, w1, a1acc[c].w);
            }
        }
        const float* a0f = (const float*)a0acc;
        const float* a1f = (const float*)a1acc;
#pragma unroll
        for (int rw = 0; rw < NR; rw++) {
            const size_t gi = (size_t)(row0 + rw) * Dd + d;
            const float x0 = F0[gi], x1 = F1[gi], fg = Fg[gi];
            const float comp = (x0 + a0f[rw] + x1 + a1f[rw] + fg) * (1.f / 3.f);
            out[gi] = blend * comp + oneminus * fg;
        }
    }
}

// ---------------- launch ----------------
extern "C" void kernel_launch(void* const* d_in, const int* in_sizes, int n_in,
                              void* d_out, int out_size)
{
    (void)in_sizes; (void)n_in; (void)out_size;
    const float* hs   = (const float*)d_in[0];
    const float* enc  = (const float*)d_in[1];
    const float* Wq   = (const float*)d_in[2];
    const float* Wk   = (const float*)d_in[3];
    const float* Wv   = (const float*)d_in[4];
    const float* Wo   = (const float*)d_in[5];
    const float* bo   = (const float*)d_in[6];
    const float* ln0g = (const float*)d_in[7];
    const float* ln0b = (const float*)d_in[8];
    const float* d0W  = (const float*)d_in[9];
    const float* d0b  = (const float*)d_in[10];
    const float* u0W  = (const float*)d_in[11];
    const float* u0b  = (const float*)d_in[12];
    const float* ln1g = (const float*)d_in[13];
    const float* ln1b = (const float*)d_in[14];
    const float* d1W  = (const float*)d_in[15];
    const float* d1b  = (const float*)d_in[16];
    const float* u1W  = (const float*)d_in[17];
    const float* u1b  = (const float*)d_in[18];
    const float* sbr  = (const float*)d_in[19];
    const int*   idx0 = (const int*)d_in[20];
    const int*   idx1 = (const int*)d_in[21];
    float* out = (float*)d_out;

    float *pq, *pk, *pv, *pFg, *pF0, *pF1, *pbl, *pT0, *pT1;
    cudaGetSymbolAddress((void**)&pq,  g_q);
    cudaGetSymbolAddress((void**)&pk,  g_k);
    cudaGetSymbolAddress((void**)&pv,  g_v);
    cudaGetSymbolAddress((void**)&pFg, g_Fg);
    cudaGetSymbolAddress((void**)&pF0, g_F0);
    cudaGetSymbolAddress((void**)&pF1, g_F1);
    cudaGetSymbolAddress((void**)&pbl, g_bl);
    cudaGetSymbolAddress((void**)&pT0, g_uT0);
    cudaGetSymbolAddress((void**)&pT1, g_uT1);

    const int att_smem = ATT_SMEM_FLOATS * (int)sizeof(float);
    const int adp_smem = ADP_SMEM_FLOATS * (int)sizeof(float);
    cudaFuncSetAttribute(attn_kernel, cudaFuncAttributeMaxDynamicSharedMemorySize, att_smem);
    cudaFuncSetAttribute(adapter_kernel, cudaFuncAttributeMaxDynamicSharedMemorySize, adp_smem);

    const int MKV = Bn * Tt;          // 616
    const int MQ  = Bn * Ss;          // 32768

    // K/V projections: (B*T, DE) x (D, DE)^T  [tf32 tensor cores]
    {
        dim3 grid(Dd / 128, (MKV + 127) / 128);
        gemm_tf32_kernel<false><<<grid, 256>>>(enc, Wk, nullptr, pk, MKV, Dd, DEe);
        gemm_tf32_kernel<false><<<grid, 256>>>(enc, Wv, nullptr, pv, MKV, Dd, DEe);
    }
    // Q projection: (B*S, D) x (D, D)^T  [tf32]
    {
        dim3 grid(Dd / 128, MQ / 128);
        gemm_tf32_kernel<false><<<grid, 256>>>(hs, Wq, nullptr, pq, MQ, Dd, Dd);
    }
    // transpose up-proj weights
    transpose_up_kernel<<<(Dd * Rr + 255) / 256, 256>>>(u0W, u1W, pT0, pT1);

    // fused attention
    {
        dim3 grid(Ss / ATT_QT, Bn * Hh);
        attn_kernel<<<grid, ATT_QT, att_smem>>>(pq, pk, pv, idx0, idx1, pFg, pF0, pF1);
    }
    // fused adapters + compose + blend
    adapter_kernel<<<MQ / NR, 256, adp_smem>>>(pF0, pF1, pFg,
                                               ln0g, ln0b, d0W, d0b, pT0, u0b,
                                               ln1g, ln1b, d1W, d1b, pT1, u1b,
                                               sbr, pbl);
    // output projection + bias [tf32]
    {
        dim3 grid(Dd / 128, MQ / 128);
        gemm_tf32_kernel<true><<<grid, 256>>>(pbl, Wo, bo, out, MQ, Dd, Dd);
    }
}

// round 3
// speedup vs baseline: 1.7823x; 1.1337x over previous
#include <cuda_runtime.h>
#include <cstdint>

// Problem constants
constexpr int Bn  = 8;
constexpr int Ss  = 4096;
constexpr int Dd  = 640;
constexpr int Tt  = 77;
constexpr int DEe = 768;
constexpr int Hh  = 10;
constexpr int HDd = 64;
constexpr int Rr  = 64;
constexpr int KB  = 768;   // fused final-GEMM K = Dd + 2*Rr
constexpr float LN_EPS = 1e-5f;

// ---------------- scratch (static device globals; no allocation) ----------------
__device__ float g_q   [(size_t)Bn*Ss*Dd];
__device__ float g_k   [(size_t)Bn*Tt*Dd];
__device__ float g_v   [(size_t)Bn*Tt*Dd];
__device__ float g_F0  [(size_t)Bn*Ss*Dd];
__device__ float g_F1  [(size_t)Bn*Ss*Dd];
__device__ float g_Abig[(size_t)Bn*Ss*KB];   // [G | h0 | h1]
__device__ float g_Wbig[(size_t)Dd*KB];      // [Wo | c1*M0 | c1*M1]
__device__ float g_bo2 [Dd];

// ================= TF32 tensor-core GEMM: C[m,n] = sum_k A[m,k]*W[n,k] (+bias) ==
// A: MxK row-major fp32.  W: NxK row-major fp32.  Inputs rounded (rna) to tf32
// during smem staging.  128x128 block tile, BK=32, 8 warps of 64x32 warp tiles,
// mma.sync.m16n8k8.tf32.  Register-prefetch double buffering over a single
// smem stage.
constexpr int GLDA = 36;   // smem row stride (32 + 4 pad)

__device__ __forceinline__ uint32_t f2tf32(float x) {
    uint32_t r;
    asm("cvt.rna.tf32.f32 %0, %1;" : "=r"(r) : "f"(x));
    return r;
}

__device__ __forceinline__ void mma_tf32(float c[4], const uint32_t a[4], const uint32_t b[2]) {
    asm volatile(
        "mma.sync.aligned.m16n8k8.row.col.f32.tf32.tf32.f32 "
        "{%0,%1,%2,%3}, {%4,%5,%6,%7}, {%8,%9}, {%0,%1,%2,%3};"
        : "+f"(c[0]), "+f"(c[1]), "+f"(c[2]), "+f"(c[3])
        : "r"(a[0]), "r"(a[1]), "r"(a[2]), "r"(a[3]), "r"(b[0]), "r"(b[1]));
}

template<bool HAS_BIAS>
__global__ __launch_bounds__(256, 1)
void gemm_tf32_kernel(const float* __restrict__ A, const float* __restrict__ W,
                      const float* __restrict__ bias, float* __restrict__ C,
                      int M, int N, int K)
{
    __shared__ uint32_t As[128 * GLDA];
    __shared__ uint32_t Bs[128 * GLDA];

    const int tid  = threadIdx.x;
    const int wid  = tid >> 5;
    const int lane = tid & 31;
    const int g    = lane >> 2;
    const int tg   = lane & 3;

    const int m0 = blockIdx.y * 128;
    const int n0 = blockIdx.x * 128;
    const int wm = (wid & 1) * 64;
    const int wn = (wid >> 1) * 32;

    const int ldrow = tid >> 3;        // 0..31 base row (x4 pages)
    const int ldseg = tid & 7;         // float4 segment within 32-k row

    float acc[4][4][4];
#pragma unroll
    for (int i = 0; i < 4; i++)
#pragma unroll
        for (int j = 0; j < 4; j++)
#pragma unroll
            for (int r = 0; r < 4; r++) acc[i][j][r] = 0.f;

    float4 pa[4], pb[4];

    auto load_tile = [&](int k0) {
#pragma unroll
        for (int p = 0; p < 4; p++) {
            const int row = ldrow + p * 32;
            const int gm = m0 + row;
            const int gn = n0 + row;
            pa[p] = make_float4(0.f, 0.f, 0.f, 0.f);
            pb[p] = make_float4(0.f, 0.f, 0.f, 0.f);
            if (gm < M) pa[p] = *(const float4*)(A + (size_t)gm * K + k0 + ldseg * 4);
            if (gn < N) pb[p] = *(const float4*)(W + (size_t)gn * K + k0 + ldseg * 4);
        }
    };
    auto store_tile = [&]() {
#pragma unroll
        for (int p = 0; p < 4; p++) {
            const int row = ldrow + p * 32;
            uint4 ta, tb;
            ta.x = f2tf32(pa[p].x); ta.y = f2tf32(pa[p].y);
            ta.z = f2tf32(pa[p].z); ta.w = f2tf32(pa[p].w);
            tb.x = f2tf32(pb[p].x); tb.y = f2tf32(pb[p].y);
            tb.z = f2tf32(pb[p].z); tb.w = f2tf32(pb[p].w);
            *(uint4*)&As[row * GLDA + ldseg * 4] = ta;
            *(uint4*)&Bs[row * GLDA + ldseg * 4] = tb;
        }
    };

    load_tile(0);
    store_tile();
    __syncthreads();

    for (int k0 = 0; k0 < K; k0 += 32) {
        const bool has_next = (k0 + 32 < K);
        if (has_next) load_tile(k0 + 32);   // prefetch into registers

#pragma unroll
        for (int ka = 0; ka < 4; ka++) {
            const int kc = ka * 8;
            uint32_t afr[4][4];
            uint32_t bfr[4][2];
#pragma unroll
            for (int i = 0; i < 4; i++) {
                const int r0 = wm + 16 * i + g;
                afr[i][0] = As[r0 * GLDA + kc + tg];
                afr[i][1] = As[(r0 + 8) * GLDA + kc + tg];
                afr[i][2] = As[r0 * GLDA + kc + tg + 4];
                afr[i][3] = As[(r0 + 8) * GLDA + kc + tg + 4];
            }
#pragma unroll
            for (int j = 0; j < 4; j++) {
                const int nrow = wn + 8 * j + g;
                bfr[j][0] = Bs[nrow * GLDA + kc + tg];
                bfr[j][1] = Bs[nrow * GLDA + kc + tg + 4];
            }
#pragma unroll
            for (int i = 0; i < 4; i++)
#pragma unroll
                for (int j = 0; j < 4; j++)
                    mma_tf32(acc[i][j], afr[i], bfr[j]);
        }
        __syncthreads();
        if (has_next) {
            store_tile();
            __syncthreads();
        }
    }

#pragma unroll
    for (int i = 0; i < 4; i++) {
        const int rowA = m0 + wm + 16 * i + g;
        const int rowB = rowA + 8;
#pragma unroll
        for (int j = 0; j < 4; j++) {
            const int col = n0 + wn + 8 * j + 2 * tg;
            float2 bv = make_float2(0.f, 0.f);
            if (HAS_BIAS) bv = *(const float2*)(bias + col);
            if (rowA < M) {
                float2 v = make_float2(acc[i][j][0] + bv.x, acc[i][j][1] + bv.y);
                *(float2*)(C + (size_t)rowA * N + col) = v;
            }
            if (rowB < M) {
                float2 v = make_float2(acc[i][j][2] + bv.x, acc[i][j][3] + bv.y);
                *(float2*)(C + (size_t)rowB * N + col) = v;
            }
        }
    }
}

// ---------------- prep: fold up-proj weights through Wo (exact fp32) ------------
// Wbig[e, 0:640]       = Wo[e, :]
// Wbig[e, 640+r]       = c1 * sum_d Wo[e,d] * u0W[d,r]
// Wbig[e, 704+r]       = c1 * sum_d Wo[e,d] * u1W[d,r]
// bo2[e]               = bo[e] + c1 * sum_d Wo[e,d] * (u0b[d]+u1b[d])
// grid(640), 64 threads (one per rank r).
__global__ __launch_bounds__(64)
void prep_kernel(const float* __restrict__ Wo,
                 const float* __restrict__ u0W, const float* __restrict__ u1W,
                 const float* __restrict__ u0b, const float* __restrict__ u1b,
                 const float* __restrict__ bo,  const float* __restrict__ sbr,
                 float* __restrict__ Wbig, float* __restrict__ bo2)
{
    __shared__ float red[64];
    const int e = blockIdx.x;
    const int r = threadIdx.x;
    const float blend = 1.f / (1.f + expf(-*sbr));
    const float c1 = blend * (1.f / 3.f);

    const float* wrow = Wo + (size_t)e * Dd;
    float* wbrow = Wbig + (size_t)e * KB;

    for (int d = r; d < Dd; d += 64) wbrow[d] = wrow[d];

    float m0 = 0.f, m1 = 0.f;
#pragma unroll 4
    for (int d = 0; d < Dd; d++) {
        const float w = wrow[d];
        m0 = fmaf(w, u0W[d * Rr + r], m0);
        m1 = fmaf(w, u1W[d * Rr + r], m1);
    }
    wbrow[Dd + r]      = c1 * m0;
    wbrow[Dd + Rr + r] = c1 * m1;

    float bp = 0.f;
    for (int d = r; d < Dd; d += 64) bp = fmaf(wrow[d], u0b[d] + u1b[d], bp);
    red[r] = bp;
    __syncthreads();
    if (r < 32) { red[r] += red[r + 32]; }
    __syncwarp();
    if (r == 0) {
        float s = 0.f;
#pragma unroll
        for (int i = 0; i < 32; i++) s += red[i];
        bo2[e] = bo[e] + c1 * s;
    }
}

// ---------------- fused attention: global + 2 entity attentions -----------------
// Writes F0, F1 (raw entity outputs, stride Dd) and G = c1*(F0+F1)+c2*Fg into
// Abig cols [0,640) (stride KB).
constexpr int ATT_QT = 128;
constexpr int QPAD   = 68;
constexpr int ATT_SMEM_FLOATS = 2 * Tt * HDd + ATT_QT * QPAD + ATT_QT * Tt;

__global__ __launch_bounds__(128)
void attn_kernel(const float* __restrict__ q, const float* __restrict__ k,
                 const float* __restrict__ v,
                 const int* __restrict__ idx0, const int* __restrict__ idx1,
                 const float* __restrict__ sbr,
                 float* __restrict__ F0, float* __restrict__ F1,
                 float* __restrict__ Abig)
{
    extern __shared__ float sm[];
    float* Ksh = sm;                       // Tt*HDd
    float* Vsh = Ksh + Tt * HDd;           // Tt*HDd
    float* Qsh = Vsh + Tt * HDd;           // ATT_QT*QPAD
    float* Psh = Qsh + ATT_QT * QPAD;      // ATT_QT*Tt
    __shared__ int si0[8], si1[8];

    const int tid = threadIdx.x;
    const int b = blockIdx.y / Hh;
    const int h = blockIdx.y % Hh;
    const int s0 = blockIdx.x * ATT_QT;

    if (tid < 8) { si0[tid] = idx0[tid]; si1[tid] = idx1[tid]; }

    const float blend = 1.f / (1.f + expf(-*sbr));
    const float c1 = blend * (1.f / 3.f);
    const float c2 = 1.f - 2.f * blend * (1.f / 3.f);

    const float* kb = k + (size_t)b * Tt * Dd + h * HDd;
    const float* vb = v + (size_t)b * Tt * Dd + h * HDd;
    for (int i = tid; i < Tt * HDd; i += ATT_QT) {
        const int t = i >> 6, d = i & 63;
        Ksh[i] = kb[(size_t)t * Dd + d];
        Vsh[i] = vb[(size_t)t * Dd + d];
    }
    const float* qb = q + (size_t)(b * Ss + s0) * Dd + h * HDd;
    for (int i = tid; i < ATT_QT * HDd; i += ATT_QT) {
        const int r = i >> 6, d = i & 63;
        Qsh[r * QPAD + d] = qb[(size_t)r * Dd + d];
    }
    __syncthreads();

    {
        float4 qr[16];
        const float4* qrow = (const float4*)&Qsh[tid * QPAD];
#pragma unroll
        for (int i = 0; i < 16; i++) qr[i] = qrow[i];

        float* prow = &Psh[tid * Tt];
        for (int t = 0; t < Tt; t++) {
            const float4* kp = (const float4*)&Ksh[t * HDd];
            float a0 = 0.f, a1 = 0.f, a2 = 0.f, a3 = 0.f;
#pragma unroll
            for (int i = 0; i < 16; i++) {
                const float4 kv = kp[i];
                a0 = fmaf(qr[i].x, kv.x, a0);
                a1 = fmaf(qr[i].y, kv.y, a1);
                a2 = fmaf(qr[i].z, kv.z, a2);
                a3 = fmaf(qr[i].w, kv.w, a3);
            }
            prow[t] = ((a0 + a1) + (a2 + a3)) * 0.125f;
        }
    }

    float* prow = &Psh[tid * Tt];

    float e0s[8], e1s[8];
#pragma unroll
    for (int j = 0; j < 8; j++) { e0s[j] = prow[si0[j]]; e1s[j] = prow[si1[j]]; }

    float m = -1e30f;
    for (int t = 0; t < Tt; t++) m = fmaxf(m, prow[t]);
    float z = 0.f;
    for (int t = 0; t < Tt; t++) { const float p = expf(prow[t] - m); prow[t] = p; z += p; }
    const float invz = 1.f / z;

    float m0 = -1e30f, m1 = -1e30f;
#pragma unroll
    for (int j = 0; j < 8; j++) { m0 = fmaxf(m0, e0s[j]); m1 = fmaxf(m1, e1s[j]); }
    float z0 = 0.f, z1 = 0.f;
#pragma unroll
    for (int j = 0; j < 8; j++) {
        e0s[j] = expf(e0s[j] - m0); z0 += e0s[j];
        e1s[j] = expf(e1s[j] - m1); z1 += e1s[j];
    }
    const float invz0 = c1 / z0, invz1 = c1 / z1;     // fold c1 into normalizers for G
    const float rz0 = 1.f / z0, rz1 = 1.f / z1;

    const int s = s0 + tid;
    const size_t fbase = (size_t)(b * Ss + s) * Dd + h * HDd;
    const size_t gbase = (size_t)(b * Ss + s) * KB + h * HDd;

    float4 Gacc[16];
#pragma unroll
    for (int i = 0; i < 16; i++) Gacc[i] = make_float4(0.f, 0.f, 0.f, 0.f);

    // entity 0
    {
        float4 acc[16];
#pragma unroll
        for (int i = 0; i < 16; i++) acc[i] = make_float4(0.f, 0.f, 0.f, 0.f);
#pragma unroll
        for (int j = 0; j < 8; j++) {
            const float p = e0s[j];
            const float4* vp = (const float4*)&Vsh[si0[j] * HDd];
#pragma unroll
            for (int i = 0; i < 16; i++) {
                const float4 vv = vp[i];
                acc[i].x = fmaf(p, vv.x, acc[i].x);
                acc[i].y = fmaf(p, vv.y, acc[i].y);
                acc[i].z = fmaf(p, vv.z, acc[i].z);
                acc[i].w = fmaf(p, vv.w, acc[i].w);
            }
        }
        float4* og = (float4*)(F0 + fbase);
#pragma unroll
        for (int i = 0; i < 16; i++) {
            og[i] = make_float4(acc[i].x * rz0, acc[i].y * rz0, acc[i].z * rz0, acc[i].w * rz0);
            Gacc[i].x = fmaf(acc[i].x, invz0, Gacc[i].x);
            Gacc[i].y = fmaf(acc[i].y, invz0, Gacc[i].y);
            Gacc[i].z = fmaf(acc[i].z, invz0, Gacc[i].z);
            Gacc[i].w = fmaf(acc[i].w, invz0, Gacc[i].w);
        }
    }
    // entity 1
    {
        float4 acc[16];
#pragma unroll
        for (int i = 0; i < 16; i++) acc[i] = make_float4(0.f, 0.f, 0.f, 0.f);
#pragma unroll
        for (int j = 0; j < 8; j++) {
            const float p = e1s[j];
            const float4* vp = (const float4*)&Vsh[si1[j] * HDd];
#pragma unroll
            for (int i = 0; i < 16; i++) {
                const float4 vv = vp[i];
                acc[i].x = fmaf(p, vv.x, acc[i].x);
                acc[i].y = fmaf(p, vv.y, acc[i].y);
                acc[i].z = fmaf(p, vv.z, acc[i].z);
                acc[i].w = fmaf(p, vv.w, acc[i].w);
            }
        }
        float4* og = (float4*)(F1 + fbase);
#pragma unroll
        for (int i = 0; i < 16; i++) {
            og[i] = make_float4(acc[i].x * rz1, acc[i].y * rz1, acc[i].z * rz1, acc[i].w * rz1);
            Gacc[i].x = fmaf(acc[i].x, invz1, Gacc[i].x);
            Gacc[i].y = fmaf(acc[i].y, invz1, Gacc[i].y);
            Gacc[i].z = fmaf(acc[i].z, invz1, Gacc[i].z);
            Gacc[i].w = fmaf(acc[i].w, invz1, Gacc[i].w);
        }
    }
    // global, accumulate c2 * softmax(V)
    {
        float4 acc[16];
#pragma unroll
        for (int i = 0; i < 16; i++) acc[i] = make_float4(0.f, 0.f, 0.f, 0.f);
        for (int t = 0; t < Tt; t++) {
            const float p = prow[t];
            const float4* vp = (const float4*)&Vsh[t * HDd];
#pragma unroll
            for (int i = 0; i < 16; i++) {
                const float4 vv = vp[i];
                acc[i].x = fmaf(p, vv.x, acc[i].x);
                acc[i].y = fmaf(p, vv.y, acc[i].y);
                acc[i].z = fmaf(p, vv.z, acc[i].z);
                acc[i].w = fmaf(p, vv.w, acc[i].w);
            }
        }
        const float cz = c2 * invz;
        float4* og = (float4*)(Abig + gbase);
#pragma unroll
        for (int i = 0; i < 16; i++) {
            og[i] = make_float4(fmaf(acc[i].x, cz, Gacc[i].x),
                                fmaf(acc[i].y, cz, Gacc[i].y),
                                fmaf(acc[i].z, cz, Gacc[i].z),
                                fmaf(acc[i].w, cz, Gacc[i].w));
        }
    }
}

// ---------------- fused adapters: LN -> down-proj -> SiLU -> h into Abig --------
constexpr int NR = 16;
constexpr int ADP_SMEM_FLOATS = 2 * NR * Dd + 2 * NR * Rr;

__global__ __launch_bounds__(256)
void adapter_kernel(const float* __restrict__ F0, const float* __restrict__ F1,
                    const float* __restrict__ ln0g, const float* __restrict__ ln0b,
                    const float* __restrict__ d0W,  const float* __restrict__ d0b,
                    const float* __restrict__ ln1g, const float* __restrict__ ln1b,
                    const float* __restrict__ d1W,  const float* __restrict__ d1b,
                    float* __restrict__ Abig)
{
    extern __shared__ float sm[];
    float* n0 = sm;
    float* n1 = n0 + NR * Dd;
    float* hsm = n1 + NR * Dd;    // [2][Rr][NR]

    const int tid = threadIdx.x;
    const int wid = tid >> 5;
    const int lane = tid & 31;
    const int row0 = blockIdx.x * NR;

    // phase 1: LayerNorm
    for (int task = wid; task < 2 * NR; task += 8) {
        const int a = task / NR;
        const int r = task % NR;
        const float* src = (a ? F1 : F0) + (size_t)(row0 + r) * Dd;
        float vals[20];
        float sum = 0.f;
#pragma unroll
        for (int i = 0; i < 20; i++) { vals[i] = src[lane + 32 * i]; sum += vals[i]; }
#pragma unroll
        for (int o = 16; o > 0; o >>= 1) sum += __shfl_xor_sync(0xffffffffu, sum, o);
        const float mean = sum * (1.f / Dd);
        float vs = 0.f;
#pragma unroll
        for (int i = 0; i < 20; i++) { const float dv = vals[i] - mean; vs = fmaf(dv, dv, vs); }
#pragma unroll
        for (int o = 16; o > 0; o >>= 1) vs += __shfl_xor_sync(0xffffffffu, vs, o);
        const float rstd = rsqrtf(vs * (1.f / Dd) + LN_EPS);
        const float* gg = a ? ln1g : ln0g;
        const float* be = a ? ln1b : ln0b;
        float* dst = (a ? n1 : n0) + r * Dd;
#pragma unroll
        for (int i = 0; i < 20; i++) {
            const int d = lane + 32 * i;
            dst[d] = (vals[i] - mean) * rstd * gg[d] + be[d];
        }
    }
    __syncthreads();

    // phase 2: down-proj + SiLU
    for (int task = wid; task < 2 * Rr; task += 8) {
        const int a = task / Rr;
        const int r = task % Rr;
        const float* W = (a ? d1W : d0W) + (size_t)r * Dd;
        const float* nn = a ? n1 : n0;
        float acc[NR];
#pragma unroll
        for (int rw = 0; rw < NR; rw++) acc[rw] = 0.f;
        for (int i = 0; i < 20; i++) {
            const float w = W[lane + 32 * i];
#pragma unroll
            for (int rw = 0; rw < NR; rw++)
                acc[rw] = fmaf(w, nn[rw * Dd + lane + 32 * i], acc[rw]);
        }
#pragma unroll
        for (int rw = 0; rw < NR; rw++) {
#pragma unroll
            for (int o = 16; o > 0; o >>= 1)
                acc[rw] += __shfl_xor_sync(0xffffffffu, acc[rw], o);
        }
        if (lane == 0) {
            const float db = (a ? d1b : d0b)[r];
            float* hdst = hsm + a * (Rr * NR) + r * NR;
#pragma unroll
            for (int rw = 0; rw < NR; rw++) {
                const float x = acc[rw] + db;
                hdst[rw] = x / (1.f + expf(-x));
            }
        }
    }
    __syncthreads();

    // phase 3: write h into Abig cols [640, 768)
    for (int idx = tid; idx < 2 * Rr * NR; idx += 256) {
        const int rw = idx >> 7;          // 0..15
        const int c  = idx & 127;         // 0..127
        const int a  = c >> 6;
        const int r  = c & 63;
        Abig[(size_t)(row0 + rw) * KB + Dd + c] = hsm[a * (Rr * NR) + r * NR + rw];
    }
}

// ---------------- launch ----------------
extern "C" void kernel_launch(void* const* d_in, const int* in_sizes, int n_in,
                              void* d_out, int out_size)
{
    (void)in_sizes; (void)n_in; (void)out_size;
    const float* hs   = (const float*)d_in[0];
    const float* enc  = (const float*)d_in[1];
    const float* Wq   = (const float*)d_in[2];
    const float* Wk   = (const float*)d_in[3];
    const float* Wv   = (const float*)d_in[4];
    const float* Wo   = (const float*)d_in[5];
    const float* bo   = (const float*)d_in[6];
    const float* ln0g = (const float*)d_in[7];
    const float* ln0b = (const float*)d_in[8];
    const float* d0W  = (const float*)d_in[9];
    const float* d0b  = (const float*)d_in[10];
    const float* u0W  = (const float*)d_in[11];
    const float* u0b  = (const float*)d_in[12];
    const float* ln1g = (const float*)d_in[13];
    const float* ln1b = (const float*)d_in[14];
    const float* d1W  = (const float*)d_in[15];
    const float* d1b  = (const float*)d_in[16];
    const float* u1W  = (const float*)d_in[17];
    const float* u1b  = (const float*)d_in[18];
    const float* sbr  = (const float*)d_in[19];
    const int*   idx0 = (const int*)d_in[20];
    const int*   idx1 = (const int*)d_in[21];
    float* out = (float*)d_out;

    float *pq, *pk, *pv, *pF0, *pF1, *pA, *pW, *pb2;
    cudaGetSymbolAddress((void**)&pq,  g_q);
    cudaGetSymbolAddress((void**)&pk,  g_k);
    cudaGetSymbolAddress((void**)&pv,  g_v);
    cudaGetSymbolAddress((void**)&pF0, g_F0);
    cudaGetSymbolAddress((void**)&pF1, g_F1);
    cudaGetSymbolAddress((void**)&pA,  g_Abig);
    cudaGetSymbolAddress((void**)&pW,  g_Wbig);
    cudaGetSymbolAddress((void**)&pb2, g_bo2);

    const int att_smem = ATT_SMEM_FLOATS * (int)sizeof(float);
    const int adp_smem = ADP_SMEM_FLOATS * (int)sizeof(float);
    cudaFuncSetAttribute(attn_kernel, cudaFuncAttributeMaxDynamicSharedMemorySize, att_smem);
    cudaFuncSetAttribute(adapter_kernel, cudaFuncAttributeMaxDynamicSharedMemorySize, adp_smem);

    const int MKV = Bn * Tt;          // 616
    const int MQ  = Bn * Ss;          // 32768

    // K/V projections
    {
        dim3 grid(Dd / 128, (MKV + 127) / 128);
        gemm_tf32_kernel<false><<<grid, 256>>>(enc, Wk, nullptr, pk, MKV, Dd, DEe);
        gemm_tf32_kernel<false><<<grid, 256>>>(enc, Wv, nullptr, pv, MKV, Dd, DEe);
    }
    // Q projection
    {
        dim3 grid(Dd / 128, MQ / 128);
        gemm_tf32_kernel<false><<<grid, 256>>>(hs, Wq, nullptr, pq, MQ, Dd, Dd);
    }
    // fold up-proj weights through Wo (exact fp32)
    prep_kernel<<<Dd, 64>>>(Wo, u0W, u1W, u0b, u1b, bo, sbr, pW, pb2);

    // fused attention (writes F0, F1, and G into Abig[:, 0:640))
    {
        dim3 grid(Ss / ATT_QT, Bn * Hh);
        attn_kernel<<<grid, ATT_QT, att_smem>>>(pq, pk, pv, idx0, idx1, sbr, pF0, pF1, pA);
    }
    // adapters: LN -> down -> SiLU -> h into Abig[:, 640:768)
    adapter_kernel<<<MQ / NR, 256, adp_smem>>>(pF0, pF1,
                                               ln0g, ln0b, d0W, d0b,
                                               ln1g, ln1b, d1W, d1b, pA);
    // single fused output GEMM: out = Abig x Wbig^T + bo2
    {
        dim3 grid(Dd / 128, MQ / 128);
        gemm_tf32_kernel<true><<<grid, 256>>>(pA, pW, pb2, out, MQ, Dd, KB);
    }
}

// round 4
// speedup vs baseline: 1.8370x; 1.0307x over previous
#include <cuda_runtime.h>
#include <cstdint>

// Problem constants
constexpr int Bn  = 8;
constexpr int Ss  = 4096;
constexpr int Dd  = 640;
constexpr int Tt  = 77;
constexpr int DEe = 768;
constexpr int Hh  = 10;
constexpr int HDd = 64;
constexpr int Rr  = 64;
constexpr int KB  = 768;   // fused final-GEMM K = Dd + 2*Rr
constexpr float LN_EPS = 1e-5f;

// ---------------- scratch (static device globals; no allocation) ----------------
__device__ float g_q   [(size_t)Bn*Ss*Dd];
__device__ float g_k   [(size_t)Bn*Tt*Dd];
__device__ float g_v   [(size_t)Bn*Tt*Dd];
__device__ float g_F0  [(size_t)Bn*Ss*Dd];
__device__ float g_F1  [(size_t)Bn*Ss*Dd];
__device__ float g_Abig[(size_t)Bn*Ss*KB];   // [G | h0 | h1]
__device__ float g_Wbig[(size_t)Dd*KB];      // [Wo | c1*M0 | c1*M1]
__device__ float g_bo2 [Dd];

// ================= TF32 tensor-core GEMM: C[m,n] = sum_k A[m,k]*W[n,k] (+bias) ==
// A: MxK row-major fp32.  W: NxK row-major fp32.  Inputs rounded (rna) to tf32
// during smem staging.  128x128 block tile, BK=32, 8 warps of 64x32 warp tiles,
// mma.sync.m16n8k8.tf32.  Two-stage smem ping-pong + register prefetch:
// exactly one __syncthreads per K-tile.
constexpr int GLDA = 36;   // smem row stride (32 + 4 pad)
constexpr int GEMM_STAGE = 128 * GLDA;             // floats per matrix per stage
constexpr int GEMM_SMEM_BYTES = 2 * 2 * GEMM_STAGE * 4;  // 73728

__device__ __forceinline__ uint32_t f2tf32(float x) {
    uint32_t r;
    asm("cvt.rna.tf32.f32 %0, %1;" : "=r"(r) : "f"(x));
    return r;
}

__device__ __forceinline__ void mma_tf32(float c[4], const uint32_t a[4], const uint32_t b[2]) {
    asm volatile(
        "mma.sync.aligned.m16n8k8.row.col.f32.tf32.tf32.f32 "
        "{%0,%1,%2,%3}, {%4,%5,%6,%7}, {%8,%9}, {%0,%1,%2,%3};"
        : "+f"(c[0]), "+f"(c[1]), "+f"(c[2]), "+f"(c[3])
        : "r"(a[0]), "r"(a[1]), "r"(a[2]), "r"(a[3]), "r"(b[0]), "r"(b[1]));
}

template<bool HAS_BIAS>
__global__ __launch_bounds__(256, 1)
void gemm_tf32_kernel(const float* __restrict__ A, const float* __restrict__ W,
                      const float* __restrict__ bias, float* __restrict__ C,
                      int M, int N, int K)
{
    extern __shared__ uint32_t smem_u[];
    // layout: [stage0 A][stage0 B][stage1 A][stage1 B]
    uint32_t* AsBase = smem_u;
    uint32_t* BsBase = smem_u + GEMM_STAGE;

    const int tid  = threadIdx.x;
    const int wid  = tid >> 5;
    const int lane = tid & 31;
    const int g    = lane >> 2;
    const int tg   = lane & 3;

    const int m0 = blockIdx.y * 128;
    const int n0 = blockIdx.x * 128;
    const int wm = (wid & 1) * 64;
    const int wn = (wid >> 1) * 32;

    const int ldrow = tid >> 3;        // 0..31 base row (x4 pages)
    const int ldseg = tid & 7;         // float4 segment within 32-k row

    float acc[4][4][4];
#pragma unroll
    for (int i = 0; i < 4; i++)
#pragma unroll
        for (int j = 0; j < 4; j++)
#pragma unroll
            for (int r = 0; r < 4; r++) acc[i][j][r] = 0.f;

    float4 pa[4], pb[4];

    auto load_tile = [&](int k0) {
#pragma unroll
        for (int p = 0; p < 4; p++) {
            const int row = ldrow + p * 32;
            const int gm = m0 + row;
            const int gn = n0 + row;
            pa[p] = make_float4(0.f, 0.f, 0.f, 0.f);
            pb[p] = make_float4(0.f, 0.f, 0.f, 0.f);
            if (gm < M) pa[p] = *(const float4*)(A + (size_t)gm * K + k0 + ldseg * 4);
            if (gn < N) pb[p] = *(const float4*)(W + (size_t)gn * K + k0 + ldseg * 4);
        }
    };
    auto store_tile = [&](int stage) {
        uint32_t* As = AsBase + stage * (2 * GEMM_STAGE);
        uint32_t* Bs = BsBase + stage * (2 * GEMM_STAGE);
#pragma unroll
        for (int p = 0; p < 4; p++) {
            const int row = ldrow + p * 32;
            uint4 ta, tb;
            ta.x = f2tf32(pa[p].x); ta.y = f2tf32(pa[p].y);
            ta.z = f2tf32(pa[p].z); ta.w = f2tf32(pa[p].w);
            tb.x = f2tf32(pb[p].x); tb.y = f2tf32(pb[p].y);
            tb.z = f2tf32(pb[p].z); tb.w = f2tf32(pb[p].w);
            *(uint4*)&As[row * GLDA + ldseg * 4] = ta;
            *(uint4*)&Bs[row * GLDA + ldseg * 4] = tb;
        }
    };

    load_tile(0);
    store_tile(0);

    int cur = 0;
    for (int k0 = 0; k0 < K; k0 += 32) {
        const bool has_next = (k0 + 32 < K);
        __syncthreads();   // stage 'cur' stores visible; prior reads of 'cur^1' done

        if (has_next) load_tile(k0 + 32);   // prefetch into registers

        const uint32_t* As = AsBase + cur * (2 * GEMM_STAGE);
        const uint32_t* Bs = BsBase + cur * (2 * GEMM_STAGE);
#pragma unroll
        for (int ka = 0; ka < 4; ka++) {
            const int kc = ka * 8;
            uint32_t afr[4][4];
            uint32_t bfr[4][2];
#pragma unroll
            for (int i = 0; i < 4; i++) {
                const int r0 = wm + 16 * i + g;
                afr[i][0] = As[r0 * GLDA + kc + tg];
                afr[i][1] = As[(r0 + 8) * GLDA + kc + tg];
                afr[i][2] = As[r0 * GLDA + kc + tg + 4];
                afr[i][3] = As[(r0 + 8) * GLDA + kc + tg + 4];
            }
#pragma unroll
            for (int j = 0; j < 4; j++) {
                const int nrow = wn + 8 * j + g;
                bfr[j][0] = Bs[nrow * GLDA + kc + tg];
                bfr[j][1] = Bs[nrow * GLDA + kc + tg + 4];
            }
#pragma unroll
            for (int i = 0; i < 4; i++)
#pragma unroll
                for (int j = 0; j < 4; j++)
                    mma_tf32(acc[i][j], afr[i], bfr[j]);
        }

        if (has_next) store_tile(cur ^ 1);  // write idle buffer; no barrier needed here
        cur ^= 1;
    }

#pragma unroll
    for (int i = 0; i < 4; i++) {
        const int rowA = m0 + wm + 16 * i + g;
        const int rowB = rowA + 8;
#pragma unroll
        for (int j = 0; j < 4; j++) {
            const int col = n0 + wn + 8 * j + 2 * tg;
            float2 bv = make_float2(0.f, 0.f);
            if (HAS_BIAS) bv = *(const float2*)(bias + col);
            if (rowA < M) {
                float2 v = make_float2(acc[i][j][0] + bv.x, acc[i][j][1] + bv.y);
                *(float2*)(C + (size_t)rowA * N + col) = v;
            }
            if (rowB < M) {
                float2 v = make_float2(acc[i][j][2] + bv.x, acc[i][j][3] + bv.y);
                *(float2*)(C + (size_t)rowB * N + col) = v;
            }
        }
    }
}

// ---------------- prep: fold up-proj weights through Wo (exact fp32) ------------
// Wbig[e, 0:640] = Wo[e,:];  Wbig[e,640+r] = c1*sum_d Wo[e,d]*u0W[d,r];
// Wbig[e,704+r] = c1*sum_d Wo[e,d]*u1W[d,r];  bo2[e] = bo[e]+c1*sum_d Wo[e,d]*(u0b+u1b)[d]
// grid(640), 256 threads: r = tid%64, d-chunk = tid/64 (4 chunks of 160), smem reduce.
__global__ __launch_bounds__(256)
void prep_kernel(const float* __restrict__ Wo,
                 const float* __restrict__ u0W, const float* __restrict__ u1W,
                 const float* __restrict__ u0b, const float* __restrict__ u1b,
                 const float* __restrict__ bo,  const float* __restrict__ sbr,
                 float* __restrict__ Wbig, float* __restrict__ bo2)
{
    __shared__ float p0[4][64];
    __shared__ float p1[4][64];
    __shared__ float pb[256];

    const int e   = blockIdx.x;
    const int tid = threadIdx.x;
    const int r   = tid & 63;
    const int ch  = tid >> 6;          // 0..3
    const float blend = 1.f / (1.f + expf(-*sbr));
    const float c1 = blend * (1.f / 3.f);

    const float* wrow = Wo + (size_t)e * Dd;
    float* wbrow = Wbig + (size_t)e * KB;

    // copy Wo row (coalesced, float4)
    for (int d4 = tid; d4 < Dd / 4; d4 += 256)
        *(float4*)(wbrow + d4 * 4) = *(const float4*)(wrow + d4 * 4);

    // partial dot products over d-chunk [ch*160, ch*160+160)
    float m0 = 0.f, m1 = 0.f, bpart = 0.f;
    const int d0 = ch * 160;
#pragma unroll 4
    for (int dd = 0; dd < 160; dd++) {
        const int d = d0 + dd;
        const float w = wrow[d];
        m0 = fmaf(w, u0W[d * Rr + r], m0);
        m1 = fmaf(w, u1W[d * Rr + r], m1);
    }
    p0[ch][r] = m0;
    p1[ch][r] = m1;

    // bias partial: d strided by 256
    {
        float s = 0.f;
        for (int d = tid; d < Dd; d += 256) s = fmaf(wrow[d], u0b[d] + u1b[d], s);
        pb[tid] = s;
    }
    __syncthreads();

    if (tid < 64) {
        const float s0 = p0[0][tid] + p0[1][tid] + p0[2][tid] + p0[3][tid];
        const float s1 = p1[0][tid] + p1[1][tid] + p1[2][tid] + p1[3][tid];
        wbrow[Dd + tid]      = c1 * s0;
        wbrow[Dd + Rr + tid] = c1 * s1;
    }
    // bias tree-reduce
    if (tid < 128) pb[tid] += pb[tid + 128];
    __syncthreads();
    if (tid < 64) pb[tid] += pb[tid + 64];
    __syncthreads();
    if (tid < 32) {
        float s = pb[tid] + pb[tid + 32];
#pragma unroll
        for (int o = 16; o > 0; o >>= 1) s += __shfl_xor_sync(0xffffffffu, s, o);
        if (tid == 0) bo2[e] = bo[e] + c1 * s;
    }
}

// ---------------- fused attention: global + 2 entity attentions -----------------
// Writes F0, F1 (raw entity outputs, stride Dd) and G = c1*(F0+F1)+c2*Fg into
// Abig cols [0,640) (stride KB).
constexpr int ATT_QT = 128;
constexpr int QPAD   = 68;
constexpr int ATT_SMEM_FLOATS = 2 * Tt * HDd + ATT_QT * QPAD + ATT_QT * Tt;

__global__ __launch_bounds__(128)
void attn_kernel(const float* __restrict__ q, const float* __restrict__ k,
                 const float* __restrict__ v,
                 const int* __restrict__ idx0, const int* __restrict__ idx1,
                 const float* __restrict__ sbr,
                 float* __restrict__ F0, float* __restrict__ F1,
                 float* __restrict__ Abig)
{
    extern __shared__ float sm[];
    float* Ksh = sm;                       // Tt*HDd
    float* Vsh = Ksh + Tt * HDd;           // Tt*HDd
    float* Qsh = Vsh + Tt * HDd;           // ATT_QT*QPAD
    float* Psh = Qsh + ATT_QT * QPAD;      // ATT_QT*Tt
    __shared__ int si0[8], si1[8];

    const int tid = threadIdx.x;
    const int b = blockIdx.y / Hh;
    const int h = blockIdx.y % Hh;
    const int s0 = blockIdx.x * ATT_QT;

    if (tid < 8) { si0[tid] = idx0[tid]; si1[tid] = idx1[tid]; }

    const float blend = 1.f / (1.f + expf(-*sbr));
    const float c1 = blend * (1.f / 3.f);
    const float c2 = 1.f - 2.f * blend * (1.f / 3.f);

    const float* kb = k + (size_t)b * Tt * Dd + h * HDd;
    const float* vb = v + (size_t)b * Tt * Dd + h * HDd;
    for (int i = tid; i < Tt * HDd; i += ATT_QT) {
        const int t = i >> 6, d = i & 63;
        Ksh[i] = kb[(size_t)t * Dd + d];
        Vsh[i] = vb[(size_t)t * Dd + d];
    }
    const float* qb = q + (size_t)(b * Ss + s0) * Dd + h * HDd;
    for (int i = tid; i < ATT_QT * HDd; i += ATT_QT) {
        const int r = i >> 6, d = i & 63;
        Qsh[r * QPAD + d] = qb[(size_t)r * Dd + d];
    }
    __syncthreads();

    {
        float4 qr[16];
        const float4* qrow = (const float4*)&Qsh[tid * QPAD];
#pragma unroll
        for (int i = 0; i < 16; i++) qr[i] = qrow[i];

        float* prow = &Psh[tid * Tt];
        for (int t = 0; t < Tt; t++) {
            const float4* kp = (const float4*)&Ksh[t * HDd];
            float a0 = 0.f, a1 = 0.f, a2 = 0.f, a3 = 0.f;
#pragma unroll
            for (int i = 0; i < 16; i++) {
                const float4 kv = kp[i];
                a0 = fmaf(qr[i].x, kv.x, a0);
                a1 = fmaf(qr[i].y, kv.y, a1);
                a2 = fmaf(qr[i].z, kv.z, a2);
                a3 = fmaf(qr[i].w, kv.w, a3);
            }
            prow[t] = ((a0 + a1) + (a2 + a3)) * 0.125f;
        }
    }

    float* prow = &Psh[tid * Tt];

    float e0s[8], e1s[8];
#pragma unroll
    for (int j = 0; j < 8; j++) { e0s[j] = prow[si0[j]]; e1s[j] = prow[si1[j]]; }

    float m = -1e30f;
    for (int t = 0; t < Tt; t++) m = fmaxf(m, prow[t]);
    float z = 0.f;
    for (int t = 0; t < Tt; t++) { const float p = expf(prow[t] - m); prow[t] = p; z += p; }
    const float invz = 1.f / z;

    float m0 = -1e30f, m1 = -1e30f;
#pragma unroll
    for (int j = 0; j < 8; j++) { m0 = fmaxf(m0, e0s[j]); m1 = fmaxf(m1, e1s[j]); }
    float z0 = 0.f, z1 = 0.f;
#pragma unroll
    for (int j = 0; j < 8; j++) {
        e0s[j] = expf(e0s[j] - m0); z0 += e0s[j];
        e1s[j] = expf(e1s[j] - m1); z1 += e1s[j];
    }
    const float invz0 = c1 / z0, invz1 = c1 / z1;
    const float rz0 = 1.f / z0, rz1 = 1.f / z1;

    const int s = s0 + tid;
    const size_t fbase = (size_t)(b * Ss + s) * Dd + h * HDd;
    const size_t gbase = (size_t)(b * Ss + s) * KB + h * HDd;

    float4 Gacc[16];
#pragma unroll
    for (int i = 0; i < 16; i++) Gacc[i] = make_float4(0.f, 0.f, 0.f, 0.f);

    // entity 0
    {
        float4 acc[16];
#pragma unroll
        for (int i = 0; i < 16; i++) acc[i] = make_float4(0.f, 0.f, 0.f, 0.f);
#pragma unroll
        for (int j = 0; j < 8; j++) {
            const float p = e0s[j];
            const float4* vp = (const float4*)&Vsh[si0[j] * HDd];
#pragma unroll
            for (int i = 0; i < 16; i++) {
                const float4 vv = vp[i];
                acc[i].x = fmaf(p, vv.x, acc[i].x);
                acc[i].y = fmaf(p, vv.y, acc[i].y);
                acc[i].z = fmaf(p, vv.z, acc[i].z);
                acc[i].w = fmaf(p, vv.w, acc[i].w);
            }
        }
        float4* og = (float4*)(F0 + fbase);
#pragma unroll
        for (int i = 0; i < 16; i++) {
            og[i] = make_float4(acc[i].x * rz0, acc[i].y * rz0, acc[i].z * rz0, acc[i].w * rz0);
            Gacc[i].x = fmaf(acc[i].x, invz0, Gacc[i].x);
            Gacc[i].y = fmaf(acc[i].y, invz0, Gacc[i].y);
            Gacc[i].z = fmaf(acc[i].z, invz0, Gacc[i].z);
            Gacc[i].w = fmaf(acc[i].w, invz0, Gacc[i].w);
        }
    }
    // entity 1
    {
        float4 acc[16];
#pragma unroll
        for (int i = 0; i < 16; i++) acc[i] = make_float4(0.f, 0.f, 0.f, 0.f);
#pragma unroll
        for (int j = 0; j < 8; j++) {
            const float p = e1s[j];
            const float4* vp = (const float4*)&Vsh[si1[j] * HDd];
#pragma unroll
            for (int i = 0; i < 16; i++) {
                const float4 vv = vp[i];
                acc[i].x = fmaf(p, vv.x, acc[i].x);
                acc[i].y = fmaf(p, vv.y, acc[i].y);
                acc[i].z = fmaf(p, vv.z, acc[i].z);
                acc[i].w = fmaf(p, vv.w, acc[i].w);
            }
        }
        float4* og = (float4*)(F1 + fbase);
#pragma unroll
        for (int i = 0; i < 16; i++) {
            og[i] = make_float4(acc[i].x * rz1, acc[i].y * rz1, acc[i].z * rz1, acc[i].w * rz1);
            Gacc[i].x = fmaf(acc[i].x, invz1, Gacc[i].x);
            Gacc[i].y = fmaf(acc[i].y, invz1, Gacc[i].y);
            Gacc[i].z = fmaf(acc[i].z, invz1, Gacc[i].z);
            Gacc[i].w = fmaf(acc[i].w, invz1, Gacc[i].w);
        }
    }
    // global, accumulate c2 * softmax(V)
    {
        float4 acc[16];
#pragma unroll
        for (int i = 0; i < 16; i++) acc[i] = make_float4(0.f, 0.f, 0.f, 0.f);
        for (int t = 0; t < Tt; t++) {
            const float p = prow[t];
            const float4* vp = (const float4*)&Vsh[t * HDd];
#pragma unroll
            for (int i = 0; i < 16; i++) {
                const float4 vv = vp[i];
                acc[i].x = fmaf(p, vv.x, acc[i].x);
                acc[i].y = fmaf(p, vv.y, acc[i].y);
                acc[i].z = fmaf(p, vv.z, acc[i].z);
                acc[i].w = fmaf(p, vv.w, acc[i].w);
            }
        }
        const float cz = c2 * invz;
        float4* og = (float4*)(Abig + gbase);
#pragma unroll
        for (int i = 0; i < 16; i++) {
            og[i] = make_float4(fmaf(acc[i].x, cz, Gacc[i].x),
                                fmaf(acc[i].y, cz, Gacc[i].y),
                                fmaf(acc[i].z, cz, Gacc[i].z),
                                fmaf(acc[i].w, cz, Gacc[i].w));
        }
    }
}

// ---------------- fused adapters: LN -> down-proj -> SiLU -> h into Abig --------
constexpr int NR = 16;
constexpr int ADP_SMEM_FLOATS = 2 * NR * Dd + 2 * NR * Rr;

__global__ __launch_bounds__(256)
void adapter_kernel(const float* __restrict__ F0, const float* __restrict__ F1,
                    const float* __restrict__ ln0g, const float* __restrict__ ln0b,
                    const float* __restrict__ d0W,  const float* __restrict__ d0b,
                    const float* __restrict__ ln1g, const float* __restrict__ ln1b,
                    const float* __restrict__ d1W,  const float* __restrict__ d1b,
                    float* __restrict__ Abig)
{
    extern __shared__ float sm[];
    float* n0 = sm;
    float* n1 = n0 + NR * Dd;
    float* hsm = n1 + NR * Dd;    // [2][Rr][NR]

    const int tid = threadIdx.x;
    const int wid = tid >> 5;
    const int lane = tid & 31;
    const int row0 = blockIdx.x * NR;

    // phase 1: LayerNorm
    for (int task = wid; task < 2 * NR; task += 8) {
        const int a = task / NR;
        const int r = task % NR;
        const float* src = (a ? F1 : F0) + (size_t)(row0 + r) * Dd;
        float vals[20];
        float sum = 0.f;
#pragma unroll
        for (int i = 0; i < 20; i++) { vals[i] = src[lane + 32 * i]; sum += vals[i]; }
#pragma unroll
        for (int o = 16; o > 0; o >>= 1) sum += __shfl_xor_sync(0xffffffffu, sum, o);
        const float mean = sum * (1.f / Dd);
        float vs = 0.f;
#pragma unroll
        for (int i = 0; i < 20; i++) { const float dv = vals[i] - mean; vs = fmaf(dv, dv, vs); }
#pragma unroll
        for (int o = 16; o > 0; o >>= 1) vs += __shfl_xor_sync(0xffffffffu, vs, o);
        const float rstd = rsqrtf(vs * (1.f / Dd) + LN_EPS);
        const float* gg = a ? ln1g : ln0g;
        const float* be = a ? ln1b : ln0b;
        float* dst = (a ? n1 : n0) + r * Dd;
#pragma unroll
        for (int i = 0; i < 20; i++) {
            const int d = lane + 32 * i;
            dst[d] = (vals[i] - mean) * rstd * gg[d] + be[d];
        }
    }
    __syncthreads();

    // phase 2: down-proj + SiLU
    for (int task = wid; task < 2 * Rr; task += 8) {
        const int a = task / Rr;
        const int r = task % Rr;
        const float* W = (a ? d1W : d0W) + (size_t)r * Dd;
        const float* nn = a ? n1 : n0;
        float acc[NR];
#pragma unroll
        for (int rw = 0; rw < NR; rw++) acc[rw] = 0.f;
        for (int i = 0; i < 20; i++) {
            const float w = W[lane + 32 * i];
#pragma unroll
            for (int rw = 0; rw < NR; rw++)
                acc[rw] = fmaf(w, nn[rw * Dd + lane + 32 * i], acc[rw]);
        }
#pragma unroll
        for (int rw = 0; rw < NR; rw++) {
#pragma unroll
            for (int o = 16; o > 0; o >>= 1)
                acc[rw] += __shfl_xor_sync(0xffffffffu, acc[rw], o);
        }
        if (lane == 0) {
            const float db = (a ? d1b : d0b)[r];
            float* hdst = hsm + a * (Rr * NR) + r * NR;
#pragma unroll
            for (int rw = 0; rw < NR; rw++) {
                const float x = acc[rw] + db;
                hdst[rw] = x / (1.f + expf(-x));
            }
        }
    }
    __syncthreads();

    // phase 3: write h into Abig cols [640, 768)
    for (int idx = tid; idx < 2 * Rr * NR; idx += 256) {
        const int rw = idx >> 7;
        const int c  = idx & 127;
        const int a  = c >> 6;
        const int r  = c & 63;
        Abig[(size_t)(row0 + rw) * KB + Dd + c] = hsm[a * (Rr * NR) + r * NR + rw];
    }
}

// ---------------- launch ----------------
extern "C" void kernel_launch(void* const* d_in, const int* in_sizes, int n_in,
                              void* d_out, int out_size)
{
    (void)in_sizes; (void)n_in; (void)out_size;
    const float* hs   = (const float*)d_in[0];
    const float* enc  = (const float*)d_in[1];
    const float* Wq   = (const float*)d_in[2];
    const float* Wk   = (const float*)d_in[3];
    const float* Wv   = (const float*)d_in[4];
    const float* Wo   = (const float*)d_in[5];
    const float* bo   = (const float*)d_in[6];
    const float* ln0g = (const float*)d_in[7];
    const float* ln0b = (const float*)d_in[8];
    const float* d0W  = (const float*)d_in[9];
    const float* d0b  = (const float*)d_in[10];
    const float* u0W  = (const float*)d_in[11];
    const float* u0b  = (const float*)d_in[12];
    const float* ln1g = (const float*)d_in[13];
    const float* ln1b = (const float*)d_in[14];
    const float* d1W  = (const float*)d_in[15];
    const float* d1b  = (const float*)d_in[16];
    const float* u1W  = (const float*)d_in[17];
    const float* u1b  = (const float*)d_in[18];
    const float* sbr  = (const float*)d_in[19];
    const int*   idx0 = (const int*)d_in[20];
    const int*   idx1 = (const int*)d_in[21];
    float* out = (float*)d_out;

    float *pq, *pk, *pv, *pF0, *pF1, *pA, *pW, *pb2;
    cudaGetSymbolAddress((void**)&pq,  g_q);
    cudaGetSymbolAddress((void**)&pk,  g_k);
    cudaGetSymbolAddress((void**)&pv,  g_v);
    cudaGetSymbolAddress((void**)&pF0, g_F0);
    cudaGetSymbolAddress((void**)&pF1, g_F1);
    cudaGetSymbolAddress((void**)&pA,  g_Abig);
    cudaGetSymbolAddress((void**)&pW,  g_Wbig);
    cudaGetSymbolAddress((void**)&pb2, g_bo2);

    const int att_smem = ATT_SMEM_FLOATS * (int)sizeof(float);
    const int adp_smem = ADP_SMEM_FLOATS * (int)sizeof(float);
    cudaFuncSetAttribute(attn_kernel, cudaFuncAttributeMaxDynamicSharedMemorySize, att_smem);
    cudaFuncSetAttribute(adapter_kernel, cudaFuncAttributeMaxDynamicSharedMemorySize, adp_smem);
    cudaFuncSetAttribute(gemm_tf32_kernel<false>, cudaFuncAttributeMaxDynamicSharedMemorySize, GEMM_SMEM_BYTES);
    cudaFuncSetAttribute(gemm_tf32_kernel<true>,  cudaFuncAttributeMaxDynamicSharedMemorySize, GEMM_SMEM_BYTES);

    const int MKV = Bn * Tt;          // 616
    const int MQ  = Bn * Ss;          // 32768

    // K/V projections
    {
        dim3 grid(Dd / 128, (MKV + 127) / 128);
        gemm_tf32_kernel<false><<<grid, 256, GEMM_SMEM_BYTES>>>(enc, Wk, nullptr, pk, MKV, Dd, DEe);
        gemm_tf32_kernel<false><<<grid, 256, GEMM_SMEM_BYTES>>>(enc, Wv, nullptr, pv, MKV, Dd, DEe);
    }
    // Q projection
    {
        dim3 grid(Dd / 128, MQ / 128);
        gemm_tf32_kernel<false><<<grid, 256, GEMM_SMEM_BYTES>>>(hs, Wq, nullptr, pq, MQ, Dd, Dd);
    }
    // fold up-proj weights through Wo (exact fp32)
    prep_kernel<<<Dd, 256>>>(Wo, u0W, u1W, u0b, u1b, bo, sbr, pW, pb2);

    // fused attention (writes F0, F1, and G into Abig[:, 0:640))
    {
        dim3 grid(Ss / ATT_QT, Bn * Hh);
        attn_kernel<<<grid, ATT_QT, att_smem>>>(pq, pk, pv, idx0, idx1, sbr, pF0, pF1, pA);
    }
    // adapters: LN -> down -> SiLU -> h into Abig[:, 640:768)
    adapter_kernel<<<MQ / NR, 256, adp_smem>>>(pF0, pF1,
                                               ln0g, ln0b, d0W, d0b,
                                               ln1g, ln1b, d1W, d1b, pA);
    // single fused output GEMM: out = Abig x Wbig^T + bo2
    {
        dim3 grid(Dd / 128, MQ / 128);
        gemm_tf32_kernel<true><<<grid, 256, GEMM_SMEM_BYTES>>>(pA, pW, pb2, out, MQ, Dd, KB);
    }
}